// round 8
// baseline (speedup 1.0000x reference)
#include <cuda_runtime.h>
#include <math.h>

// Problem constants (fixed by setup_inputs)
#define BB 128
#define TT 32
#define HH 128
#define NNEI 16
#define NHEAD 4
#define LL 544                      // (NNEI+1)*TT
#define SCALE 0.08838834764831845f  // 1/sqrt(128)

// Scratch (device globals — no allocations allowed)
__device__ float g_m[NHEAD * BB * HH];    // m[n][b][h]
__device__ float g_W2[NHEAD * HH * HH];   // W2[n][h][e]
__device__ float g_u[BB * NHEAD * HH];    // u[b][n][h]
__device__ int   g_maskmode;              // 0=int32, 1=uint8, 2=float32

__device__ __forceinline__ float warpRedSum(float v) {
    v += __shfl_xor_sync(0xffffffffu, v, 16);
    v += __shfl_xor_sync(0xffffffffu, v, 8);
    v += __shfl_xor_sync(0xffffffffu, v, 4);
    v += __shfl_xor_sync(0xffffffffu, v, 2);
    v += __shfl_xor_sync(0xffffffffu, v, 1);
    return v;
}
__device__ __forceinline__ float warpRedMax(float v) {
    v = fmaxf(v, __shfl_xor_sync(0xffffffffu, v, 16));
    v = fmaxf(v, __shfl_xor_sync(0xffffffffu, v, 8));
    v = fmaxf(v, __shfl_xor_sync(0xffffffffu, v, 4));
    v = fmaxf(v, __shfl_xor_sync(0xffffffffu, v, 2));
    v = fmaxf(v, __shfl_xor_sync(0xffffffffu, v, 1));
    return v;
}

// ---------------------------------------------------------------------------
// Kernel 0: detect mask dtype from raw words. Scans the first BB*LL/4 32-bit
// words (safe lower bound for every candidate dtype).
//   any byte > 1                       -> float32 (1.0f has bytes 0x80, 0x3F)
//   else any word with upper bytes set -> uint8 bool (bytes 0/1, random fill)
//   else                               -> int32 (words are 0 or 1)
// ---------------------------------------------------------------------------
__global__ __launch_bounds__(256) void detect_kernel(const unsigned int* __restrict__ mw)
{
    __shared__ int fHigh;   // some byte > 1
    __shared__ int fMulti;  // some word has nonzero upper 3 bytes
    if (threadIdx.x == 0) { fHigh = 0; fMulti = 0; }
    __syncthreads();

    const int NW = BB * LL / 4;   // 17408
    int lh = 0, lm = 0;
    for (int i = threadIdx.x; i < NW; i += 256) {
        unsigned int w = mw[i];
        unsigned int b0 = w & 0xFFu, b1 = (w >> 8) & 0xFFu,
                     b2 = (w >> 16) & 0xFFu, b3 = (w >> 24) & 0xFFu;
        if (b0 > 1u || b1 > 1u || b2 > 1u || b3 > 1u) lh = 1;
        if ((w & 0xFFFFFF00u) != 0u) lm = 1;
    }
    if (lh) atomicOr(&fHigh, 1);
    if (lm) atomicOr(&fMulti, 1);
    __syncthreads();
    if (threadIdx.x == 0)
        g_maskmode = fHigh ? 2 : (fMulti ? 1 : 0);
}

// ---------------------------------------------------------------------------
// Kernel 1: prep
//   blocks [0,128):  m[n][b][h] (n = blk>>5, 4 batches per block)
//   blocks [128,192): W2[n][h][e] = sum_d wvs[n][h][d] * prjw[e][n*128+d]
// ---------------------------------------------------------------------------
__global__ __launch_bounds__(128) void prep_kernel(
    const float* __restrict__ node,   // [B,T,H]
    const float* __restrict__ wqs,    // [NH,H,H]
    const float* __restrict__ wks,    // [NH,H,H]
    const float* __restrict__ wvs,    // [NH,H,H]
    const float* __restrict__ prjw,   // [H, NH*H]
    const int*   __restrict__ stepp)
{
    const int tid = threadIdx.x;
    const int ts = stepp[0];

    if (blockIdx.x < 128) {
        __shared__ float q_sm[4 * 128];
        __shared__ float qs_sm[4 * 128];
        const int n  = blockIdx.x >> 5;
        const int b0 = (blockIdx.x & 31) * 4;

        #pragma unroll
        for (int b = 0; b < 4; b++)
            q_sm[b * 128 + tid] = node[(size_t)(b0 + b) * (TT * HH) + (size_t)ts * HH + tid];
        __syncthreads();

        // stage 1: q_s[b][d] = sum_h q[b][h]*wqs[n][h][d], thread = d
        {
            float a0 = 0.f, a1 = 0.f, a2 = 0.f, a3 = 0.f;
            const float* wq = wqs + (size_t)n * HH * HH;
            #pragma unroll 4
            for (int t = 0; t < 128; t++) {
                float w = wq[t * 128 + tid];
                a0 += q_sm[0 * 128 + t] * w;
                a1 += q_sm[1 * 128 + t] * w;
                a2 += q_sm[2 * 128 + t] * w;
                a3 += q_sm[3 * 128 + t] * w;
            }
            qs_sm[0 * 128 + tid] = a0;
            qs_sm[1 * 128 + tid] = a1;
            qs_sm[2 * 128 + tid] = a2;
            qs_sm[3 * 128 + tid] = a3;
        }
        __syncthreads();

        // stage 2: m[b][h] = sum_d q_s[b][d]*wks[n][h][d], thread = h
        {
            float a0 = 0.f, a1 = 0.f, a2 = 0.f, a3 = 0.f;
            const float* wk = wks + (size_t)n * HH * HH + (size_t)tid * 128;
            #pragma unroll 4
            for (int d = 0; d < 128; d++) {
                float w = wk[d];
                a0 += qs_sm[0 * 128 + d] * w;
                a1 += qs_sm[1 * 128 + d] * w;
                a2 += qs_sm[2 * 128 + d] * w;
                a3 += qs_sm[3 * 128 + d] * w;
            }
            g_m[((size_t)n * 128 + (b0 + 0)) * 128 + tid] = a0;
            g_m[((size_t)n * 128 + (b0 + 1)) * 128 + tid] = a1;
            g_m[((size_t)n * 128 + (b0 + 2)) * 128 + tid] = a2;
            g_m[((size_t)n * 128 + (b0 + 3)) * 128 + tid] = a3;
        }
    } else {
        __shared__ float wv_sm[8 * 128];
        const int j  = blockIdx.x - 128;
        const int n  = j >> 4;
        const int h0 = (j & 15) * 8;

        #pragma unroll
        for (int k = 0; k < 8; k++)
            wv_sm[k * 128 + tid] = wvs[(size_t)n * HH * HH + (size_t)(h0 + k) * 128 + tid];
        __syncthreads();

        float acc[8];
        #pragma unroll
        for (int k = 0; k < 8; k++) acc[k] = 0.f;

        const float* pw = prjw + (size_t)tid * (NHEAD * HH) + (size_t)n * HH;  // e = tid
        #pragma unroll 4
        for (int d = 0; d < 128; d++) {
            float p = pw[d];
            #pragma unroll
            for (int k = 0; k < 8; k++) acc[k] += wv_sm[k * 128 + d] * p;
        }
        #pragma unroll
        for (int k = 0; k < 8; k++)
            g_W2[((size_t)n * 128 + (h0 + k)) * 128 + tid] = acc[k];
    }
}

// ---------------------------------------------------------------------------
// Kernel 2: main attention. One block per batch b, 512 threads.
// ---------------------------------------------------------------------------
__global__ __launch_bounds__(512) void main_kernel(
    const float* __restrict__ node,    // [B,T,H]
    const float* __restrict__ neigh,   // [B,N*T,H]
    const void*  __restrict__ maskraw, // [B,L], dtype per g_maskmode
    float* __restrict__ outp)
{
    __shared__ float m_sm[NHEAD * HH];      // 512 f
    __shared__ float SA[NHEAD * LL];        // 2176 f (scores -> probs)
    __shared__ float part[16 * NHEAD * HH]; // 8192 f
    __shared__ float red[16];
    __shared__ float red2[16];

    const int tid = threadIdx.x;
    const int b = blockIdx.x;
    const int lane = tid & 31;
    const int wid = tid >> 5;
    const float NEG_INF = __int_as_float(0xff800000u);
    const int mode = g_maskmode;

    m_sm[tid] = g_m[((size_t)(tid >> 7) * 128 + b) * 128 + (tid & 127)];
    __syncthreads();

    float4 mr0 = reinterpret_cast<const float4*>(m_sm)[0 * 32 + lane];
    float4 mr1 = reinterpret_cast<const float4*>(m_sm)[1 * 32 + lane];
    float4 mr2 = reinterpret_cast<const float4*>(m_sm)[2 * 32 + lane];
    float4 mr3 = reinterpret_cast<const float4*>(m_sm)[3 * 32 + lane];

    const float4* nodeB  = reinterpret_cast<const float4*>(node  + (size_t)b * TT * HH);
    const float4* neighB = reinterpret_cast<const float4*>(neigh + (size_t)b * NNEI * TT * HH);

    // ---- pass 1: scores ----
    for (int i = 0; i < 34; i++) {
        int l = wid + (i << 4);
        const float4* row = (l < TT) ? (nodeB + (size_t)l * 32) : (neighB + (size_t)(l - TT) * 32);
        float4 v = row[lane];
        float s0 = v.x * mr0.x + v.y * mr0.y + v.z * mr0.z + v.w * mr0.w;
        float s1 = v.x * mr1.x + v.y * mr1.y + v.z * mr1.z + v.w * mr1.w;
        float s2 = v.x * mr2.x + v.y * mr2.y + v.z * mr2.z + v.w * mr2.w;
        float s3 = v.x * mr3.x + v.y * mr3.y + v.z * mr3.z + v.w * mr3.w;
        s0 = warpRedSum(s0);
        s1 = warpRedSum(s1);
        s2 = warpRedSum(s2);
        s3 = warpRedSum(s3);
        if (lane == 0) {
            size_t mi = (size_t)b * LL + l;
            bool mk;
            if (mode == 0)      mk = (reinterpret_cast<const int*>(maskraw)[mi] != 0);
            else if (mode == 1) mk = (reinterpret_cast<const unsigned char*>(maskraw)[mi] != 0);
            else                mk = (reinterpret_cast<const float*>(maskraw)[mi] != 0.f);
            SA[0 * LL + l] = mk ? NEG_INF : s0 * SCALE;
            SA[1 * LL + l] = mk ? NEG_INF : s1 * SCALE;
            SA[2 * LL + l] = mk ? NEG_INF : s2 * SCALE;
            SA[3 * LL + l] = mk ? NEG_INF : s3 * SCALE;
        }
    }
    __syncthreads();

    // ---- softmax per head (128 threads per head) ----
    {
        const int g = tid >> 7;
        const int t = tid & 127;
        const int wig = (tid >> 5) & 3;
        float mx = NEG_INF;
        for (int l = t; l < LL; l += 128) mx = fmaxf(mx, SA[g * LL + l]);
        mx = warpRedMax(mx);
        if (lane == 0) red[g * 4 + wig] = mx;
        __syncthreads();
        mx = fmaxf(fmaxf(red[g * 4], red[g * 4 + 1]), fmaxf(red[g * 4 + 2], red[g * 4 + 3]));

        float sm = 0.f;
        for (int l = t; l < LL; l += 128) {
            float e = expf(SA[g * LL + l] - mx);
            SA[g * LL + l] = e;
            sm += e;
        }
        sm = warpRedSum(sm);
        if (lane == 0) red2[g * 4 + wig] = sm;
        __syncthreads();
        float inv = 1.f / (red2[g * 4] + red2[g * 4 + 1] + red2[g * 4 + 2] + red2[g * 4 + 3]);
        for (int l = t; l < LL; l += 128) SA[g * LL + l] *= inv;
    }
    __syncthreads();

    // ---- slf_attn output: sum over heads ----
    for (int l = tid; l < LL; l += 512)
        outp[BB * HH + (size_t)b * LL + l] = SA[l] + SA[LL + l] + SA[2 * LL + l] + SA[3 * LL + l];

    // ---- pass 2: u[n][h] = sum_l A[n][l] * kv[l][h] ----
    {
        const int l0 = wid * 34;
        float4 a0 = make_float4(0, 0, 0, 0), a1 = a0, a2 = a0, a3 = a0;
        for (int j = 0; j < 34; j++) {
            int l = l0 + j;
            const float4* row = (l < TT) ? (nodeB + (size_t)l * 32) : (neighB + (size_t)(l - TT) * 32);
            float4 v = row[lane];
            float c0 = SA[l], c1 = SA[LL + l], c2 = SA[2 * LL + l], c3 = SA[3 * LL + l];
            a0.x += c0 * v.x; a0.y += c0 * v.y; a0.z += c0 * v.z; a0.w += c0 * v.w;
            a1.x += c1 * v.x; a1.y += c1 * v.y; a1.z += c1 * v.z; a1.w += c1 * v.w;
            a2.x += c2 * v.x; a2.y += c2 * v.y; a2.z += c2 * v.z; a2.w += c2 * v.w;
            a3.x += c3 * v.x; a3.y += c3 * v.y; a3.z += c3 * v.z; a3.w += c3 * v.w;
        }
        float4* P = reinterpret_cast<float4*>(part);
        P[(wid * 4 + 0) * 32 + lane] = a0;
        P[(wid * 4 + 1) * 32 + lane] = a1;
        P[(wid * 4 + 2) * 32 + lane] = a2;
        P[(wid * 4 + 3) * 32 + lane] = a3;
    }
    __syncthreads();
    {
        const int n = tid >> 7, h = tid & 127;
        float u = 0.f;
        #pragma unroll
        for (int g = 0; g < 16; g++) u += part[(g * 4 + n) * 128 + h];
        g_u[(size_t)b * 512 + n * 128 + h] = u;
    }
}

// ---------------------------------------------------------------------------
// Kernel 3: epilogue (folded W2). proj = u @ W2 + bias + residual q, LayerNorm.
// 2 batches per block, 512 threads.
// ---------------------------------------------------------------------------
__global__ __launch_bounds__(512) void epi_kernel(
    const float* __restrict__ node,
    const float* __restrict__ prjb,
    const float* __restrict__ gamma,
    const float* __restrict__ beta,
    const int*   __restrict__ stepp,
    float* __restrict__ outp)
{
    __shared__ float u_sm[1024];
    __shared__ float psum[1024];
    __shared__ float lred[8];
    __shared__ float lred2[8];

    const int tid = threadIdx.x;
    const int ts = stepp[0];
    const size_t ubase = (size_t)blockIdx.x * 2 * 512;

    u_sm[tid]       = g_u[ubase + tid];
    u_sm[tid + 512] = g_u[ubase + 512 + tid];
    __syncthreads();

    const int s = tid >> 7;     // 0..3: quarter of the 512-deep dot
    const int e = tid & 127;
    float a0 = 0.f, a1 = 0.f;
    const int i0 = s * 128;
    #pragma unroll 4
    for (int i = i0; i < i0 + 128; ++i) {
        float w = g_W2[(size_t)i * 128 + e];
        a0 += u_sm[i] * w;
        a1 += u_sm[512 + i] * w;
    }
    psum[(s * 2 + 0) * 128 + e] = a0;
    psum[(s * 2 + 1) * 128 + e] = a1;
    __syncthreads();

    const int b = (tid >> 7) & 1;
    float x = 0.f;
    if (tid < 256) {
        x = psum[(0 * 2 + b) * 128 + e] + psum[(1 * 2 + b) * 128 + e]
          + psum[(2 * 2 + b) * 128 + e] + psum[(3 * 2 + b) * 128 + e]
          + prjb[e]
          + node[(size_t)(blockIdx.x * 2 + b) * (TT * HH) + (size_t)ts * HH + e];
    }
    float ws = warpRedSum(x);
    if (tid < 256 && (tid & 31) == 0) lred[tid >> 5] = ws;
    __syncthreads();
    float mean = (lred[b * 4] + lred[b * 4 + 1] + lred[b * 4 + 2] + lred[b * 4 + 3]) * (1.f / 128.f);
    float d = x - mean;
    float wq = warpRedSum(d * d);
    if (tid < 256 && (tid & 31) == 0) lred2[tid >> 5] = wq;
    __syncthreads();
    float var = (lred2[b * 4] + lred2[b * 4 + 1] + lred2[b * 4 + 2] + lred2[b * 4 + 3]) * (1.f / 128.f);
    if (tid < 256) {
        outp[(size_t)(blockIdx.x * 2 + b) * 128 + e] = d * rsqrtf(var + 1e-6f) * gamma[e] + beta[e];
    }
}

extern "C" void kernel_launch(void* const* d_in, const int* in_sizes, int n_in,
                              void* d_out, int out_size)
{
    const float* node  = (const float*)d_in[0];
    const float* neigh = (const float*)d_in[1];
    const void*  mask  = d_in[2];
    const int*   step  = (const int*)d_in[3];
    const float* wqs   = (const float*)d_in[4];
    const float* wks   = (const float*)d_in[5];
    const float* wvs   = (const float*)d_in[6];
    const float* prjw  = (const float*)d_in[7];
    const float* prjb  = (const float*)d_in[8];
    const float* gamma = (const float*)d_in[9];
    const float* beta  = (const float*)d_in[10];
    float* outp = (float*)d_out;

    detect_kernel<<<1, 256>>>((const unsigned int*)mask);
    prep_kernel<<<192, 128>>>(node, wqs, wks, wvs, prjw, step);
    main_kernel<<<128, 512>>>(node, neigh, mask, outp);
    epi_kernel<<<64, 512>>>(node, prjb, gamma, beta, step, outp);
}

// round 9
// speedup vs baseline: 1.3353x; 1.3353x over previous
#include <cuda_runtime.h>
#include <math.h>

// Problem constants (fixed by setup_inputs)
#define BB 128
#define TT 32
#define HH 128
#define NNEI 16
#define NHEAD 4
#define LL 544                      // (NNEI+1)*TT
#define SCALE 0.08838834764831845f  // 1/sqrt(128)

// Scratch (device globals — no allocations allowed)
__device__ float g_m[NHEAD * BB * HH];    // m[n][b][h]
__device__ float g_W2[NHEAD * HH * HH];   // W2[n*128+h][e]
__device__ int   g_fHigh[4];              // mask-dtype detection votes
__device__ int   g_fMulti[4];

__device__ __forceinline__ float warpRedSum(float v) {
    v += __shfl_xor_sync(0xffffffffu, v, 16);
    v += __shfl_xor_sync(0xffffffffu, v, 8);
    v += __shfl_xor_sync(0xffffffffu, v, 4);
    v += __shfl_xor_sync(0xffffffffu, v, 2);
    v += __shfl_xor_sync(0xffffffffu, v, 1);
    return v;
}
__device__ __forceinline__ float warpRedMax(float v) {
    v = fmaxf(v, __shfl_xor_sync(0xffffffffu, v, 16));
    v = fmaxf(v, __shfl_xor_sync(0xffffffffu, v, 8));
    v = fmaxf(v, __shfl_xor_sync(0xffffffffu, v, 4));
    v = fmaxf(v, __shfl_xor_sync(0xffffffffu, v, 2));
    v = fmaxf(v, __shfl_xor_sync(0xffffffffu, v, 1));
    return v;
}

// ---------------------------------------------------------------------------
// Kernel 1: prep (196 blocks x 128 threads)
//   blocks [0,128):   m[n][b][h]    (n = blk>>5, 4 batches per block)
//   blocks [128,192): W2[n*128+h][e] = sum_d wvs[n][h][d] * prjw[e][n*128+d]
//   blocks [192,196): mask dtype detection, quarter q = blk-192 (no atomics:
//                     each block overwrites its own vote slot every launch)
// ---------------------------------------------------------------------------
__global__ __launch_bounds__(128) void prep_kernel(
    const float* __restrict__ node,   // [B,T,H]
    const float* __restrict__ wqs,    // [NH,H,H]
    const float* __restrict__ wks,    // [NH,H,H]
    const float* __restrict__ wvs,    // [NH,H,H]
    const float* __restrict__ prjw,   // [H, NH*H]
    const unsigned int* __restrict__ maskw,
    const int*   __restrict__ stepp)
{
    const int tid = threadIdx.x;

    if (blockIdx.x < 128) {
        const int ts = stepp[0];
        __shared__ float q_sm[4 * 128];
        __shared__ float qs_sm[4 * 128];
        const int n  = blockIdx.x >> 5;
        const int b0 = (blockIdx.x & 31) * 4;

        #pragma unroll
        for (int b = 0; b < 4; b++)
            q_sm[b * 128 + tid] = node[(size_t)(b0 + b) * (TT * HH) + (size_t)ts * HH + tid];
        __syncthreads();

        // stage 1: q_s[b][d] = sum_h q[b][h]*wqs[n][h][d], thread = d (coalesced)
        {
            float a0 = 0.f, a1 = 0.f, a2 = 0.f, a3 = 0.f;
            const float* wq = wqs + (size_t)n * HH * HH;
            #pragma unroll 8
            for (int t = 0; t < 128; t++) {
                float w = wq[t * 128 + tid];
                a0 += q_sm[0 * 128 + t] * w;
                a1 += q_sm[1 * 128 + t] * w;
                a2 += q_sm[2 * 128 + t] * w;
                a3 += q_sm[3 * 128 + t] * w;
            }
            qs_sm[0 * 128 + tid] = a0;
            qs_sm[1 * 128 + tid] = a1;
            qs_sm[2 * 128 + tid] = a2;
            qs_sm[3 * 128 + tid] = a3;
        }
        __syncthreads();

        // stage 2: m[b][h] = sum_d q_s[b][d]*wks[n][h][d], thread = h, float4 over d
        {
            float a0 = 0.f, a1 = 0.f, a2 = 0.f, a3 = 0.f;
            const float4* wk4 = reinterpret_cast<const float4*>(
                wks + (size_t)n * HH * HH + (size_t)tid * 128);
            #pragma unroll 8
            for (int d4 = 0; d4 < 32; d4++) {
                float4 w = wk4[d4];
                int d = d4 * 4;
                a0 += qs_sm[0*128+d]*w.x + qs_sm[0*128+d+1]*w.y + qs_sm[0*128+d+2]*w.z + qs_sm[0*128+d+3]*w.w;
                a1 += qs_sm[1*128+d]*w.x + qs_sm[1*128+d+1]*w.y + qs_sm[1*128+d+2]*w.z + qs_sm[1*128+d+3]*w.w;
                a2 += qs_sm[2*128+d]*w.x + qs_sm[2*128+d+1]*w.y + qs_sm[2*128+d+2]*w.z + qs_sm[2*128+d+3]*w.w;
                a3 += qs_sm[3*128+d]*w.x + qs_sm[3*128+d+1]*w.y + qs_sm[3*128+d+2]*w.z + qs_sm[3*128+d+3]*w.w;
            }
            g_m[((size_t)n * 128 + (b0 + 0)) * 128 + tid] = a0;
            g_m[((size_t)n * 128 + (b0 + 1)) * 128 + tid] = a1;
            g_m[((size_t)n * 128 + (b0 + 2)) * 128 + tid] = a2;
            g_m[((size_t)n * 128 + (b0 + 3)) * 128 + tid] = a3;
        }
    } else if (blockIdx.x < 192) {
        __shared__ float wv_sm[8 * 128];
        const int j  = blockIdx.x - 128;
        const int n  = j >> 4;
        const int h0 = (j & 15) * 8;

        #pragma unroll
        for (int k = 0; k < 8; k++)
            wv_sm[k * 128 + tid] = wvs[(size_t)n * HH * HH + (size_t)(h0 + k) * 128 + tid];
        __syncthreads();

        float acc[8];
        #pragma unroll
        for (int k = 0; k < 8; k++) acc[k] = 0.f;

        const float4* pw4 = reinterpret_cast<const float4*>(
            prjw + (size_t)tid * (NHEAD * HH) + (size_t)n * HH);  // e = tid
        #pragma unroll 4
        for (int d4 = 0; d4 < 32; d4++) {
            float4 p = pw4[d4];
            int d = d4 * 4;
            #pragma unroll
            for (int k = 0; k < 8; k++)
                acc[k] += wv_sm[k*128+d]*p.x + wv_sm[k*128+d+1]*p.y
                        + wv_sm[k*128+d+2]*p.z + wv_sm[k*128+d+3]*p.w;
        }
        #pragma unroll
        for (int k = 0; k < 8; k++)
            g_W2[((size_t)n * 128 + (h0 + k)) * 128 + tid] = acc[k];
    } else {
        // mask dtype detection on quarter q.
        //   any byte > 1                        -> float32 (1.0f = 00 00 80 3F)
        //   else any word with upper bytes set  -> uint8 bool
        //   else                                -> int32
        __shared__ int sH, sM;
        if (tid == 0) { sH = 0; sM = 0; }
        __syncthreads();
        const int q = blockIdx.x - 192;
        const int QW = (BB * LL / 4) / 4;   // 4352 words per quarter
        const unsigned int* p = maskw + q * QW;
        int lh = 0, lm = 0;
        #pragma unroll 4
        for (int i = tid; i < QW; i += 128) {
            unsigned int w = p[i];
            unsigned int b0 = w & 0xFFu, b1 = (w >> 8) & 0xFFu,
                         b2 = (w >> 16) & 0xFFu, b3 = (w >> 24) & 0xFFu;
            if (b0 > 1u || b1 > 1u || b2 > 1u || b3 > 1u) lh = 1;
            if ((w & 0xFFFFFF00u) != 0u) lm = 1;
        }
        if (lh) atomicOr(&sH, 1);
        if (lm) atomicOr(&sM, 1);
        __syncthreads();
        if (tid == 0) { g_fHigh[q] = sH; g_fMulti[q] = sM; }
    }
}

// ---------------------------------------------------------------------------
// Kernel 2: fused attention + projection + LayerNorm. One block per batch b,
// 512 threads.
// ---------------------------------------------------------------------------
__global__ __launch_bounds__(512) void main_kernel(
    const float* __restrict__ node,    // [B,T,H]
    const float* __restrict__ neigh,   // [B,N*T,H]
    const void*  __restrict__ maskraw, // [B,L]
    const float* __restrict__ prjb,
    const float* __restrict__ gamma,
    const float* __restrict__ beta,
    const int*   __restrict__ stepp,
    float* __restrict__ outp)
{
    __shared__ float m_sm[NHEAD * HH];       // 2 KB
    __shared__ float SA[NHEAD * LL];         // 8.5 KB (scores -> probs)
    __shared__ float part[16 * NHEAD * HH];  // 32 KB (pass2 partials, then proj psum)
    __shared__ float u_sm[NHEAD * HH];       // 2 KB
    __shared__ float red[16];
    __shared__ float red2[16];

    const int tid = threadIdx.x;
    const int b = blockIdx.x;
    const int lane = tid & 31;
    const int wid = tid >> 5;
    const float NEG_INF = __int_as_float(0xff800000u);

    const int mode = (g_fHigh[0] | g_fHigh[1] | g_fHigh[2] | g_fHigh[3]) ? 2
                   : ((g_fMulti[0] | g_fMulti[1] | g_fMulti[2] | g_fMulti[3]) ? 1 : 0);

    m_sm[tid] = g_m[((size_t)(tid >> 7) * 128 + b) * 128 + (tid & 127)];
    __syncthreads();

    float4 mr0 = reinterpret_cast<const float4*>(m_sm)[0 * 32 + lane];
    float4 mr1 = reinterpret_cast<const float4*>(m_sm)[1 * 32 + lane];
    float4 mr2 = reinterpret_cast<const float4*>(m_sm)[2 * 32 + lane];
    float4 mr3 = reinterpret_cast<const float4*>(m_sm)[3 * 32 + lane];

    const float4* nodeB  = reinterpret_cast<const float4*>(node  + (size_t)b * TT * HH);
    const float4* neighB = reinterpret_cast<const float4*>(neigh + (size_t)b * NNEI * TT * HH);

    // ---- pass 1: scores (warp per l; 11-shuffle 4-head reduction) ----
    for (int i = 0; i < 34; i++) {
        int l = wid + (i << 4);
        const float4* row = (l < TT) ? (nodeB + (size_t)l * 32) : (neighB + (size_t)(l - TT) * 32);
        float4 v = row[lane];
        float s0 = v.x * mr0.x + v.y * mr0.y + v.z * mr0.z + v.w * mr0.w;
        float s1 = v.x * mr1.x + v.y * mr1.y + v.z * mr1.z + v.w * mr1.w;
        float s2 = v.x * mr2.x + v.y * mr2.y + v.z * mr2.z + v.w * mr2.w;
        float s3 = v.x * mr3.x + v.y * mr3.y + v.z * mr3.z + v.w * mr3.w;
        // quad-level butterfly on all heads
        s0 += __shfl_xor_sync(0xffffffffu, s0, 1);  s0 += __shfl_xor_sync(0xffffffffu, s0, 2);
        s1 += __shfl_xor_sync(0xffffffffu, s1, 1);  s1 += __shfl_xor_sync(0xffffffffu, s1, 2);
        s2 += __shfl_xor_sync(0xffffffffu, s2, 1);  s2 += __shfl_xor_sync(0xffffffffu, s2, 2);
        s3 += __shfl_xor_sync(0xffffffffu, s3, 1);  s3 += __shfl_xor_sync(0xffffffffu, s3, 2);
        // lane&3 selects its head's quad-sum; reduce across the 8 quads
        int q = lane & 3;
        float w = (q == 0) ? s0 : (q == 1) ? s1 : (q == 2) ? s2 : s3;
        w += __shfl_xor_sync(0xffffffffu, w, 4);
        w += __shfl_xor_sync(0xffffffffu, w, 8);
        w += __shfl_xor_sync(0xffffffffu, w, 16);
        if (lane < 4) {
            size_t mi = (size_t)b * LL + l;
            bool mk;
            if (mode == 0)      mk = (reinterpret_cast<const int*>(maskraw)[mi] != 0);
            else if (mode == 1) mk = (reinterpret_cast<const unsigned char*>(maskraw)[mi] != 0);
            else                mk = (reinterpret_cast<const float*>(maskraw)[mi] != 0.f);
            SA[lane * LL + l] = mk ? NEG_INF : w * SCALE;
        }
    }
    __syncthreads();

    // ---- softmax per head (128 threads per head) ----
    {
        const int g = tid >> 7;
        const int t = tid & 127;
        const int wig = (tid >> 5) & 3;
        float mx = NEG_INF;
        for (int l = t; l < LL; l += 128) mx = fmaxf(mx, SA[g * LL + l]);
        mx = warpRedMax(mx);
        if (lane == 0) red[g * 4 + wig] = mx;
        __syncthreads();
        mx = fmaxf(fmaxf(red[g * 4], red[g * 4 + 1]), fmaxf(red[g * 4 + 2], red[g * 4 + 3]));

        float sm = 0.f;
        for (int l = t; l < LL; l += 128) {
            float e = __expf(SA[g * LL + l] - mx);
            SA[g * LL + l] = e;
            sm += e;
        }
        sm = warpRedSum(sm);
        if (lane == 0) red2[g * 4 + wig] = sm;
        __syncthreads();
        float inv = 1.f / (red2[g * 4] + red2[g * 4 + 1] + red2[g * 4 + 2] + red2[g * 4 + 3]);
        for (int l = t; l < LL; l += 128) SA[g * LL + l] *= inv;
    }
    __syncthreads();

    // ---- slf_attn output: sum over heads ----
    for (int l = tid; l < LL; l += 512)
        outp[BB * HH + (size_t)b * LL + l] = SA[l] + SA[LL + l] + SA[2 * LL + l] + SA[3 * LL + l];

    // ---- pass 2: u[n][h] = sum_l A[n][l] * kv[l][h] ----
    {
        const int l0 = wid * 34;
        float4 a0 = make_float4(0, 0, 0, 0), a1 = a0, a2 = a0, a3 = a0;
        for (int j = 0; j < 34; j++) {
            int l = l0 + j;
            const float4* row = (l < TT) ? (nodeB + (size_t)l * 32) : (neighB + (size_t)(l - TT) * 32);
            float4 v = row[lane];
            float c0 = SA[l], c1 = SA[LL + l], c2 = SA[2 * LL + l], c3 = SA[3 * LL + l];
            a0.x += c0 * v.x; a0.y += c0 * v.y; a0.z += c0 * v.z; a0.w += c0 * v.w;
            a1.x += c1 * v.x; a1.y += c1 * v.y; a1.z += c1 * v.z; a1.w += c1 * v.w;
            a2.x += c2 * v.x; a2.y += c2 * v.y; a2.z += c2 * v.z; a2.w += c2 * v.w;
            a3.x += c3 * v.x; a3.y += c3 * v.y; a3.z += c3 * v.z; a3.w += c3 * v.w;
        }
        float4* P = reinterpret_cast<float4*>(part);
        P[(wid * 4 + 0) * 32 + lane] = a0;
        P[(wid * 4 + 1) * 32 + lane] = a1;
        P[(wid * 4 + 2) * 32 + lane] = a2;
        P[(wid * 4 + 3) * 32 + lane] = a3;
    }
    __syncthreads();
    {
        const int n = tid >> 7, h = tid & 127;
        float u = 0.f;
        #pragma unroll
        for (int g = 0; g < 16; g++) u += part[(g * 4 + n) * 128 + h];
        u_sm[n * 128 + h] = u;
    }
    __syncthreads();

    // ---- fused projection: proj[e] = sum_i u[i] * W2[i][e] ----
    // warp wid handles i in [wid*32, wid*32+32); lane owns float4 of e.
    {
        const float4* W24 = reinterpret_cast<const float4*>(g_W2);
        float4 acc = make_float4(0, 0, 0, 0);
        const int i0 = wid * 32;
        #pragma unroll 8
        for (int k = 0; k < 32; k++) {
            int i = i0 + k;
            float uv = u_sm[i];
            float4 wv = W24[(size_t)i * 32 + lane];
            acc.x += uv * wv.x; acc.y += uv * wv.y; acc.z += uv * wv.z; acc.w += uv * wv.w;
        }
        reinterpret_cast<float4*>(part)[wid * 32 + lane] = acc;  // part[wid*128 + e]
    }
    __syncthreads();

    // ---- residual + LayerNorm (threads 0..127; all threads shuffle) ----
    {
        const int ts = stepp[0];
        float x = 0.f;
        if (tid < 128) {
            float p = 0.f;
            #pragma unroll
            for (int w = 0; w < 16; w++) p += part[w * 128 + tid];
            x = p + prjb[tid] + node[(size_t)b * (TT * HH) + (size_t)ts * HH + tid];
        }
        float ws = warpRedSum(x);
        if (tid < 128 && lane == 0) red[tid >> 5] = ws;
        __syncthreads();
        float mean = (red[0] + red[1] + red[2] + red[3]) * (1.f / 128.f);
        float d = x - mean;
        float wq = warpRedSum(d * d);
        if (tid < 128 && lane == 0) red2[tid >> 5] = wq;
        __syncthreads();
        if (tid < 128) {
            float var = (red2[0] + red2[1] + red2[2] + red2[3]) * (1.f / 128.f);
            outp[(size_t)b * 128 + tid] = d * rsqrtf(var + 1e-6f) * gamma[tid] + beta[tid];
        }
    }
}

extern "C" void kernel_launch(void* const* d_in, const int* in_sizes, int n_in,
                              void* d_out, int out_size)
{
    const float* node  = (const float*)d_in[0];
    const float* neigh = (const float*)d_in[1];
    const void*  mask  = d_in[2];
    const int*   step  = (const int*)d_in[3];
    const float* wqs   = (const float*)d_in[4];
    const float* wks   = (const float*)d_in[5];
    const float* wvs   = (const float*)d_in[6];
    const float* prjw  = (const float*)d_in[7];
    const float* prjb  = (const float*)d_in[8];
    const float* gamma = (const float*)d_in[9];
    const float* beta  = (const float*)d_in[10];
    float* outp = (float*)d_out;

    prep_kernel<<<196, 128>>>(node, wqs, wks, wvs, prjw,
                              (const unsigned int*)mask, step);
    main_kernel<<<128, 512>>>(node, neigh, mask, prjb, gamma, beta, step, outp);
}

// round 10
// speedup vs baseline: 1.5882x; 1.1894x over previous
#include <cuda_runtime.h>
#include <math.h>

// Problem constants (fixed by setup_inputs)
#define BB 128
#define TT 32
#define HH 128
#define NNEI 16
#define NHEAD 4
#define LL 544                      // (NNEI+1)*TT
#define CH 4                        // l-chunks
#define CL 136                      // l per chunk (LL/CH)
#define SCALE 0.08838834764831845f  // 1/sqrt(128)

// Scratch (device globals — no allocations allowed)
__device__ float g_m[NHEAD * BB * HH];      // m[n][b][h]
__device__ float g_W2[NHEAD * HH * HH];     // W2[i][e]
__device__ float g_S[BB * NHEAD * LL];      // S[b][n][l] (masked, scaled)
__device__ float g_upart[CH * BB * 512];    // u partials per chunk
__device__ int   g_fHigh[4];                // mask-dtype detection votes
__device__ int   g_fMulti[4];

__device__ __forceinline__ float warpRedSum(float v) {
    v += __shfl_xor_sync(0xffffffffu, v, 16);
    v += __shfl_xor_sync(0xffffffffu, v, 8);
    v += __shfl_xor_sync(0xffffffffu, v, 4);
    v += __shfl_xor_sync(0xffffffffu, v, 2);
    v += __shfl_xor_sync(0xffffffffu, v, 1);
    return v;
}
__device__ __forceinline__ float warpRedMax(float v) {
    v = fmaxf(v, __shfl_xor_sync(0xffffffffu, v, 16));
    v = fmaxf(v, __shfl_xor_sync(0xffffffffu, v, 8));
    v = fmaxf(v, __shfl_xor_sync(0xffffffffu, v, 4));
    v = fmaxf(v, __shfl_xor_sync(0xffffffffu, v, 2));
    v = fmaxf(v, __shfl_xor_sync(0xffffffffu, v, 1));
    return v;
}

__device__ __forceinline__ int mask_mode() {
    return (g_fHigh[0] | g_fHigh[1] | g_fHigh[2] | g_fHigh[3]) ? 2
         : ((g_fMulti[0] | g_fMulti[1] | g_fMulti[2] | g_fMulti[3]) ? 1 : 0);
}

// ---------------------------------------------------------------------------
// Kernel 1: prep (196 blocks x 128 threads)
//   blocks [0,128):   m[n][b][h]    (n = blk>>5, 4 batches per block)
//   blocks [128,192): W2[n*128+h][e] = sum_d wvs[n][h][d] * prjw[e][n*128+d]
//   blocks [192,196): mask dtype detection (per-quarter vote slots)
// ---------------------------------------------------------------------------
__global__ __launch_bounds__(128) void prep_kernel(
    const float* __restrict__ node,   // [B,T,H]
    const float* __restrict__ wqs,    // [NH,H,H]
    const float* __restrict__ wks,    // [NH,H,H]
    const float* __restrict__ wvs,    // [NH,H,H]
    const float* __restrict__ prjw,   // [H, NH*H]
    const unsigned int* __restrict__ maskw,
    const int*   __restrict__ stepp)
{
    const int tid = threadIdx.x;

    if (blockIdx.x < 128) {
        const int ts = stepp[0];
        __shared__ float q_sm[4 * 128];
        __shared__ float qs_sm[4 * 128];
        const int n  = blockIdx.x >> 5;
        const int b0 = (blockIdx.x & 31) * 4;

        #pragma unroll
        for (int b = 0; b < 4; b++)
            q_sm[b * 128 + tid] = node[(size_t)(b0 + b) * (TT * HH) + (size_t)ts * HH + tid];
        __syncthreads();

        // stage 1: q_s[b][d] = sum_h q[b][h]*wqs[n][h][d], thread = d
        {
            float a0 = 0.f, a1 = 0.f, a2 = 0.f, a3 = 0.f;
            const float* wq = wqs + (size_t)n * HH * HH;
            #pragma unroll 8
            for (int t = 0; t < 128; t++) {
                float w = wq[t * 128 + tid];
                a0 += q_sm[0 * 128 + t] * w;
                a1 += q_sm[1 * 128 + t] * w;
                a2 += q_sm[2 * 128 + t] * w;
                a3 += q_sm[3 * 128 + t] * w;
            }
            qs_sm[0 * 128 + tid] = a0;
            qs_sm[1 * 128 + tid] = a1;
            qs_sm[2 * 128 + tid] = a2;
            qs_sm[3 * 128 + tid] = a3;
        }
        __syncthreads();

        // stage 2: m[b][h] = sum_d q_s[b][d]*wks[n][h][d], thread = h
        {
            float a0 = 0.f, a1 = 0.f, a2 = 0.f, a3 = 0.f;
            const float4* wk4 = reinterpret_cast<const float4*>(
                wks + (size_t)n * HH * HH + (size_t)tid * 128);
            #pragma unroll 8
            for (int d4 = 0; d4 < 32; d4++) {
                float4 w = wk4[d4];
                int d = d4 * 4;
                a0 += qs_sm[0*128+d]*w.x + qs_sm[0*128+d+1]*w.y + qs_sm[0*128+d+2]*w.z + qs_sm[0*128+d+3]*w.w;
                a1 += qs_sm[1*128+d]*w.x + qs_sm[1*128+d+1]*w.y + qs_sm[1*128+d+2]*w.z + qs_sm[1*128+d+3]*w.w;
                a2 += qs_sm[2*128+d]*w.x + qs_sm[2*128+d+1]*w.y + qs_sm[2*128+d+2]*w.z + qs_sm[2*128+d+3]*w.w;
                a3 += qs_sm[3*128+d]*w.x + qs_sm[3*128+d+1]*w.y + qs_sm[3*128+d+2]*w.z + qs_sm[3*128+d+3]*w.w;
            }
            g_m[((size_t)n * 128 + (b0 + 0)) * 128 + tid] = a0;
            g_m[((size_t)n * 128 + (b0 + 1)) * 128 + tid] = a1;
            g_m[((size_t)n * 128 + (b0 + 2)) * 128 + tid] = a2;
            g_m[((size_t)n * 128 + (b0 + 3)) * 128 + tid] = a3;
        }
    } else if (blockIdx.x < 192) {
        __shared__ float wv_sm[8 * 128];
        const int j  = blockIdx.x - 128;
        const int n  = j >> 4;
        const int h0 = (j & 15) * 8;

        #pragma unroll
        for (int k = 0; k < 8; k++)
            wv_sm[k * 128 + tid] = wvs[(size_t)n * HH * HH + (size_t)(h0 + k) * 128 + tid];
        __syncthreads();

        float acc[8];
        #pragma unroll
        for (int k = 0; k < 8; k++) acc[k] = 0.f;

        const float4* pw4 = reinterpret_cast<const float4*>(
            prjw + (size_t)tid * (NHEAD * HH) + (size_t)n * HH);  // e = tid
        #pragma unroll 4
        for (int d4 = 0; d4 < 32; d4++) {
            float4 p = pw4[d4];
            int d = d4 * 4;
            #pragma unroll
            for (int k = 0; k < 8; k++)
                acc[k] += wv_sm[k*128+d]*p.x + wv_sm[k*128+d+1]*p.y
                        + wv_sm[k*128+d+2]*p.z + wv_sm[k*128+d+3]*p.w;
        }
        #pragma unroll
        for (int k = 0; k < 8; k++)
            g_W2[((size_t)n * 128 + (h0 + k)) * 128 + tid] = acc[k];
    } else {
        __shared__ int sH, sM;
        if (tid == 0) { sH = 0; sM = 0; }
        __syncthreads();
        const int q = blockIdx.x - 192;
        const int QW = (BB * LL / 4) / 4;   // 4352 words per quarter
        const unsigned int* p = maskw + q * QW;
        int lh = 0, lm = 0;
        #pragma unroll 4
        for (int i = tid; i < QW; i += 128) {
            unsigned int w = p[i];
            unsigned int b0 = w & 0xFFu, b1 = (w >> 8) & 0xFFu,
                         b2 = (w >> 16) & 0xFFu, b3 = (w >> 24) & 0xFFu;
            if (b0 > 1u || b1 > 1u || b2 > 1u || b3 > 1u) lh = 1;
            if ((w & 0xFFFFFF00u) != 0u) lm = 1;
        }
        if (lh) atomicOr(&sH, 1);
        if (lm) atomicOr(&sM, 1);
        __syncthreads();
        if (tid == 0) { g_fHigh[q] = sH; g_fMulti[q] = sM; }
    }
}

// ---------------------------------------------------------------------------
// Kernel 2: scores. grid (128 b, 4 c) x 256 threads. Block (b,c) computes
// S[b][n][l] for l in [c*136, (c+1)*136), masked and scaled.
// Warp per l (8 warps x 17 l's each), 11-shuffle 4-head reduction.
// ---------------------------------------------------------------------------
__global__ __launch_bounds__(256) void score_kernel(
    const float* __restrict__ node,    // [B,T,H]
    const float* __restrict__ neigh,   // [B,N*T,H]
    const void*  __restrict__ maskraw)
{
    __shared__ float m_sm[NHEAD * HH];
    const int tid = threadIdx.x;
    const int b = blockIdx.x;
    const int c = blockIdx.y;
    const int lane = tid & 31;
    const int wid = tid >> 5;
    const float NEG_INF = __int_as_float(0xff800000u);
    const int mode = mask_mode();

    m_sm[tid]       = g_m[((size_t)(tid >> 7) * 128 + b) * 128 + (tid & 127)];
    m_sm[tid + 256] = g_m[((size_t)((tid + 256) >> 7) * 128 + b) * 128 + ((tid + 256) & 127)];
    __syncthreads();

    float4 mr0 = reinterpret_cast<const float4*>(m_sm)[0 * 32 + lane];
    float4 mr1 = reinterpret_cast<const float4*>(m_sm)[1 * 32 + lane];
    float4 mr2 = reinterpret_cast<const float4*>(m_sm)[2 * 32 + lane];
    float4 mr3 = reinterpret_cast<const float4*>(m_sm)[3 * 32 + lane];

    const float4* nodeB  = reinterpret_cast<const float4*>(node  + (size_t)b * TT * HH);
    const float4* neighB = reinterpret_cast<const float4*>(neigh + (size_t)b * NNEI * TT * HH);

    const int lbase = c * CL + wid * 17;
    #pragma unroll 1
    for (int j = 0; j < 17; j++) {
        int l = lbase + j;
        const float4* row = (l < TT) ? (nodeB + (size_t)l * 32) : (neighB + (size_t)(l - TT) * 32);
        float4 v = row[lane];
        float s0 = v.x * mr0.x + v.y * mr0.y + v.z * mr0.z + v.w * mr0.w;
        float s1 = v.x * mr1.x + v.y * mr1.y + v.z * mr1.z + v.w * mr1.w;
        float s2 = v.x * mr2.x + v.y * mr2.y + v.z * mr2.z + v.w * mr2.w;
        float s3 = v.x * mr3.x + v.y * mr3.y + v.z * mr3.z + v.w * mr3.w;
        s0 += __shfl_xor_sync(0xffffffffu, s0, 1);  s0 += __shfl_xor_sync(0xffffffffu, s0, 2);
        s1 += __shfl_xor_sync(0xffffffffu, s1, 1);  s1 += __shfl_xor_sync(0xffffffffu, s1, 2);
        s2 += __shfl_xor_sync(0xffffffffu, s2, 1);  s2 += __shfl_xor_sync(0xffffffffu, s2, 2);
        s3 += __shfl_xor_sync(0xffffffffu, s3, 1);  s3 += __shfl_xor_sync(0xffffffffu, s3, 2);
        int q = lane & 3;
        float w = (q == 0) ? s0 : (q == 1) ? s1 : (q == 2) ? s2 : s3;
        w += __shfl_xor_sync(0xffffffffu, w, 4);
        w += __shfl_xor_sync(0xffffffffu, w, 8);
        w += __shfl_xor_sync(0xffffffffu, w, 16);
        if (lane < 4) {
            size_t mi = (size_t)b * LL + l;
            bool mk;
            if (mode == 0)      mk = (reinterpret_cast<const int*>(maskraw)[mi] != 0);
            else if (mode == 1) mk = (reinterpret_cast<const unsigned char*>(maskraw)[mi] != 0);
            else                mk = (reinterpret_cast<const float*>(maskraw)[mi] != 0.f);
            g_S[((size_t)b * NHEAD + lane) * LL + l] = mk ? NEG_INF : w * SCALE;
        }
    }
}

// ---------------------------------------------------------------------------
// Kernel 3: softmax (recomputed per block) + slf_attn chunk + weighted sum.
// grid (128 b, 4 c) x 256 threads. Writes u-partials for its l-chunk.
// ---------------------------------------------------------------------------
__global__ __launch_bounds__(256) void ctx_kernel(
    const float* __restrict__ node,
    const float* __restrict__ neigh,
    float* __restrict__ outp)
{
    __shared__ float SA[NHEAD * LL];        // 8.5 KB
    __shared__ float part[8 * NHEAD * HH];  // 16 KB
    __shared__ float red[8];
    __shared__ float red2[8];

    const int tid = threadIdx.x;
    const int b = blockIdx.x;
    const int c = blockIdx.y;
    const int lane = tid & 31;
    const int wid = tid >> 5;
    const float NEG_INF = __int_as_float(0xff800000u);

    // load S[b] (2176 floats, coalesced float4)
    {
        const float4* Sg = reinterpret_cast<const float4*>(g_S + (size_t)b * NHEAD * LL);
        float4* SA4 = reinterpret_cast<float4*>(SA);
        for (int i = tid; i < NHEAD * LL / 4; i += 256) SA4[i] = Sg[i];
    }
    __syncthreads();

    // softmax: 2 warps per head; warp covers l = half*32+lane step 64
    {
        const int n = wid >> 1;
        const int half = wid & 1;
        float mx = NEG_INF;
        for (int l = half * 32 + lane; l < LL; l += 64) mx = fmaxf(mx, SA[n * LL + l]);
        mx = warpRedMax(mx);
        if (lane == 0) red[wid] = mx;
        __syncthreads();
        mx = fmaxf(red[n * 2], red[n * 2 + 1]);

        float sm = 0.f;
        for (int l = half * 32 + lane; l < LL; l += 64) {
            float e = __expf(SA[n * LL + l] - mx);
            SA[n * LL + l] = e;
            sm += e;
        }
        sm = warpRedSum(sm);
        if (lane == 0) red2[wid] = sm;
        __syncthreads();
        float inv = 1.f / (red2[n * 2] + red2[n * 2 + 1]);
        for (int l = half * 32 + lane; l < LL; l += 64) SA[n * LL + l] *= inv;
    }
    __syncthreads();

    // slf_attn for own chunk
    if (tid < CL) {
        int l = c * CL + tid;
        outp[BB * HH + (size_t)b * LL + l] = SA[l] + SA[LL + l] + SA[2 * LL + l] + SA[3 * LL + l];
    }

    // weighted sum over own chunk: warp wid handles 17 l's
    const float4* nodeB  = reinterpret_cast<const float4*>(node  + (size_t)b * TT * HH);
    const float4* neighB = reinterpret_cast<const float4*>(neigh + (size_t)b * NNEI * TT * HH);
    {
        const int l0 = c * CL + wid * 17;
        float4 a0 = make_float4(0, 0, 0, 0), a1 = a0, a2 = a0, a3 = a0;
        #pragma unroll 1
        for (int j = 0; j < 17; j++) {
            int l = l0 + j;
            const float4* row = (l < TT) ? (nodeB + (size_t)l * 32) : (neighB + (size_t)(l - TT) * 32);
            float4 v = row[lane];
            float c0 = SA[l], c1 = SA[LL + l], c2 = SA[2 * LL + l], c3 = SA[3 * LL + l];
            a0.x += c0 * v.x; a0.y += c0 * v.y; a0.z += c0 * v.z; a0.w += c0 * v.w;
            a1.x += c1 * v.x; a1.y += c1 * v.y; a1.z += c1 * v.z; a1.w += c1 * v.w;
            a2.x += c2 * v.x; a2.y += c2 * v.y; a2.z += c2 * v.z; a2.w += c2 * v.w;
            a3.x += c3 * v.x; a3.y += c3 * v.y; a3.z += c3 * v.z; a3.w += c3 * v.w;
        }
        float4* P = reinterpret_cast<float4*>(part);
        P[(wid * 4 + 0) * 32 + lane] = a0;
        P[(wid * 4 + 1) * 32 + lane] = a1;
        P[(wid * 4 + 2) * 32 + lane] = a2;
        P[(wid * 4 + 3) * 32 + lane] = a3;
    }
    __syncthreads();
    // reduce 8 warp-partials; 256 threads cover 512 (n,h) outputs, 2 each
    {
        #pragma unroll
        for (int r = 0; r < 2; r++) {
            int idx = tid + r * 256;
            int n = idx >> 7, h = idx & 127;
            float u = 0.f;
            #pragma unroll
            for (int g = 0; g < 8; g++) u += part[(g * 4 + n) * 128 + h];
            g_upart[((size_t)c * BB + b) * 512 + idx] = u;
        }
    }
}

// ---------------------------------------------------------------------------
// Kernel 4: finish. grid 128 x 512. Sum u-partials, proj = u @ W2 + bias
// + residual, LayerNorm.
// ---------------------------------------------------------------------------
__global__ __launch_bounds__(512) void finish_kernel(
    const float* __restrict__ node,
    const float* __restrict__ prjb,
    const float* __restrict__ gamma,
    const float* __restrict__ beta,
    const int*   __restrict__ stepp,
    float* __restrict__ outp)
{
    __shared__ float u_sm[512];
    __shared__ float part[16 * HH];   // 8 KB
    __shared__ float red[4];
    __shared__ float red2[4];

    const int tid = threadIdx.x;
    const int b = blockIdx.x;
    const int lane = tid & 31;
    const int wid = tid >> 5;

    u_sm[tid] = g_upart[((size_t)0 * BB + b) * 512 + tid]
              + g_upart[((size_t)1 * BB + b) * 512 + tid]
              + g_upart[((size_t)2 * BB + b) * 512 + tid]
              + g_upart[((size_t)3 * BB + b) * 512 + tid];
    __syncthreads();

    // projection: warp wid handles i in [wid*32, wid*32+32); lane owns float4 of e
    {
        const float4* W24 = reinterpret_cast<const float4*>(g_W2);
        float4 acc = make_float4(0, 0, 0, 0);
        const int i0 = wid * 32;
        #pragma unroll 8
        for (int k = 0; k < 32; k++) {
            int i = i0 + k;
            float uv = u_sm[i];
            float4 wv = W24[(size_t)i * 32 + lane];
            acc.x += uv * wv.x; acc.y += uv * wv.y; acc.z += uv * wv.z; acc.w += uv * wv.w;
        }
        reinterpret_cast<float4*>(part)[wid * 32 + lane] = acc;
    }
    __syncthreads();

    // residual + LayerNorm (threads 0..127 produce; all shuffle)
    {
        const int ts = stepp[0];
        float x = 0.f;
        if (tid < 128) {
            float p = 0.f;
            #pragma unroll
            for (int w = 0; w < 16; w++) p += part[w * 128 + tid];
            x = p + prjb[tid] + node[(size_t)b * (TT * HH) + (size_t)ts * HH + tid];
        }
        float ws = warpRedSum(x);
        if (tid < 128 && lane == 0) red[wid] = ws;
        __syncthreads();
        float mean = (red[0] + red[1] + red[2] + red[3]) * (1.f / 128.f);
        float d = x - mean;
        float wq = warpRedSum(d * d);
        if (tid < 128 && lane == 0) red2[wid] = wq;
        __syncthreads();
        if (tid < 128) {
            float var = (red2[0] + red2[1] + red2[2] + red2[3]) * (1.f / 128.f);
            outp[(size_t)b * 128 + tid] = d * rsqrtf(var + 1e-6f) * gamma[tid] + beta[tid];
        }
    }
}

extern "C" void kernel_launch(void* const* d_in, const int* in_sizes, int n_in,
                              void* d_out, int out_size)
{
    const float* node  = (const float*)d_in[0];
    const float* neigh = (const float*)d_in[1];
    const void*  mask  = d_in[2];
    const int*   step  = (const int*)d_in[3];
    const float* wqs   = (const float*)d_in[4];
    const float* wks   = (const float*)d_in[5];
    const float* wvs   = (const float*)d_in[6];
    const float* prjw  = (const float*)d_in[7];
    const float* prjb  = (const float*)d_in[8];
    const float* gamma = (const float*)d_in[9];
    const float* beta  = (const float*)d_in[10];
    float* outp = (float*)d_out;

    prep_kernel<<<196, 128>>>(node, wqs, wks, wvs, prjw,
                              (const unsigned int*)mask, step);
    score_kernel<<<dim3(128, CH), 256>>>(node, neigh, mask);
    ctx_kernel<<<dim3(128, CH), 256>>>(node, neigh, outp);
    finish_kernel<<<128, 512>>>(node, prjb, gamma, beta, step, outp);
}

// round 11
// speedup vs baseline: 1.5992x; 1.0069x over previous
#include <cuda_runtime.h>
#include <math.h>

// Problem constants (fixed by setup_inputs)
#define BB 128
#define TT 32
#define HH 128
#define NNEI 16
#define NHEAD 4
#define LL 544                      // (NNEI+1)*TT
#define CH 4                        // l-chunks
#define CL 136                      // l per chunk (LL/CH)
#define SCALE 0.08838834764831845f  // 1/sqrt(128)

// Scratch (device globals — no allocations allowed)
__device__ float g_m[NHEAD * BB * HH];      // m[n][b][h]
__device__ float g_W2[NHEAD * HH * HH];     // W2[i][e]
__device__ float g_S[BB * NHEAD * LL];      // S[b][n][l] (masked, scaled)
__device__ float g_upart[CH * BB * 512];    // u partials per chunk
__device__ int   g_cnt1[BB];                // stage-1 barrier (zero-init, reset each launch)
__device__ int   g_cnt2[BB];                // stage-2 barrier
__device__ int   g_fHigh[4];                // mask-dtype detection votes
__device__ int   g_fMulti[4];

__device__ __forceinline__ float warpRedSum(float v) {
    v += __shfl_xor_sync(0xffffffffu, v, 16);
    v += __shfl_xor_sync(0xffffffffu, v, 8);
    v += __shfl_xor_sync(0xffffffffu, v, 4);
    v += __shfl_xor_sync(0xffffffffu, v, 2);
    v += __shfl_xor_sync(0xffffffffu, v, 1);
    return v;
}
__device__ __forceinline__ float warpRedMax(float v) {
    v = fmaxf(v, __shfl_xor_sync(0xffffffffu, v, 16));
    v = fmaxf(v, __shfl_xor_sync(0xffffffffu, v, 8));
    v = fmaxf(v, __shfl_xor_sync(0xffffffffu, v, 4));
    v = fmaxf(v, __shfl_xor_sync(0xffffffffu, v, 2));
    v = fmaxf(v, __shfl_xor_sync(0xffffffffu, v, 1));
    return v;
}

__device__ __forceinline__ int mask_mode() {
    return (g_fHigh[0] | g_fHigh[1] | g_fHigh[2] | g_fHigh[3]) ? 2
         : ((g_fMulti[0] | g_fMulti[1] | g_fMulti[2] | g_fMulti[3]) ? 1 : 0);
}

// ---------------------------------------------------------------------------
// Kernel 1: prep (196 blocks x 128 threads)
//   blocks [0,128):   m[n][b][h]    (n = blk>>5, 4 batches per block)
//   blocks [128,192): W2[n*128+h][e] = sum_d wvs[n][h][d] * prjw[e][n*128+d]
//   blocks [192,196): mask dtype detection (per-quarter vote slots)
// ---------------------------------------------------------------------------
__global__ __launch_bounds__(128) void prep_kernel(
    const float* __restrict__ node,   // [B,T,H]
    const float* __restrict__ wqs,    // [NH,H,H]
    const float* __restrict__ wks,    // [NH,H,H]
    const float* __restrict__ wvs,    // [NH,H,H]
    const float* __restrict__ prjw,   // [H, NH*H]
    const unsigned int* __restrict__ maskw,
    const int*   __restrict__ stepp)
{
    const int tid = threadIdx.x;

    if (blockIdx.x < 128) {
        const int ts = stepp[0];
        __shared__ float q_sm[4 * 128];
        __shared__ float qs_sm[4 * 128];
        const int n  = blockIdx.x >> 5;
        const int b0 = (blockIdx.x & 31) * 4;

        #pragma unroll
        for (int b = 0; b < 4; b++)
            q_sm[b * 128 + tid] = node[(size_t)(b0 + b) * (TT * HH) + (size_t)ts * HH + tid];
        __syncthreads();

        {
            float a0 = 0.f, a1 = 0.f, a2 = 0.f, a3 = 0.f;
            const float* wq = wqs + (size_t)n * HH * HH;
            #pragma unroll 8
            for (int t = 0; t < 128; t++) {
                float w = wq[t * 128 + tid];
                a0 += q_sm[0 * 128 + t] * w;
                a1 += q_sm[1 * 128 + t] * w;
                a2 += q_sm[2 * 128 + t] * w;
                a3 += q_sm[3 * 128 + t] * w;
            }
            qs_sm[0 * 128 + tid] = a0;
            qs_sm[1 * 128 + tid] = a1;
            qs_sm[2 * 128 + tid] = a2;
            qs_sm[3 * 128 + tid] = a3;
        }
        __syncthreads();

        {
            float a0 = 0.f, a1 = 0.f, a2 = 0.f, a3 = 0.f;
            const float4* wk4 = reinterpret_cast<const float4*>(
                wks + (size_t)n * HH * HH + (size_t)tid * 128);
            #pragma unroll 8
            for (int d4 = 0; d4 < 32; d4++) {
                float4 w = wk4[d4];
                int d = d4 * 4;
                a0 += qs_sm[0*128+d]*w.x + qs_sm[0*128+d+1]*w.y + qs_sm[0*128+d+2]*w.z + qs_sm[0*128+d+3]*w.w;
                a1 += qs_sm[1*128+d]*w.x + qs_sm[1*128+d+1]*w.y + qs_sm[1*128+d+2]*w.z + qs_sm[1*128+d+3]*w.w;
                a2 += qs_sm[2*128+d]*w.x + qs_sm[2*128+d+1]*w.y + qs_sm[2*128+d+2]*w.z + qs_sm[2*128+d+3]*w.w;
                a3 += qs_sm[3*128+d]*w.x + qs_sm[3*128+d+1]*w.y + qs_sm[3*128+d+2]*w.z + qs_sm[3*128+d+3]*w.w;
            }
            g_m[((size_t)n * 128 + (b0 + 0)) * 128 + tid] = a0;
            g_m[((size_t)n * 128 + (b0 + 1)) * 128 + tid] = a1;
            g_m[((size_t)n * 128 + (b0 + 2)) * 128 + tid] = a2;
            g_m[((size_t)n * 128 + (b0 + 3)) * 128 + tid] = a3;
        }
    } else if (blockIdx.x < 192) {
        __shared__ float wv_sm[8 * 128];
        const int j  = blockIdx.x - 128;
        const int n  = j >> 4;
        const int h0 = (j & 15) * 8;

        #pragma unroll
        for (int k = 0; k < 8; k++)
            wv_sm[k * 128 + tid] = wvs[(size_t)n * HH * HH + (size_t)(h0 + k) * 128 + tid];
        __syncthreads();

        float acc[8];
        #pragma unroll
        for (int k = 0; k < 8; k++) acc[k] = 0.f;

        const float4* pw4 = reinterpret_cast<const float4*>(
            prjw + (size_t)tid * (NHEAD * HH) + (size_t)n * HH);  // e = tid
        #pragma unroll 4
        for (int d4 = 0; d4 < 32; d4++) {
            float4 p = pw4[d4];
            int d = d4 * 4;
            #pragma unroll
            for (int k = 0; k < 8; k++)
                acc[k] += wv_sm[k*128+d]*p.x + wv_sm[k*128+d+1]*p.y
                        + wv_sm[k*128+d+2]*p.z + wv_sm[k*128+d+3]*p.w;
        }
        #pragma unroll
        for (int k = 0; k < 8; k++)
            g_W2[((size_t)n * 128 + (h0 + k)) * 128 + tid] = acc[k];
    } else {
        __shared__ int sH, sM;
        if (tid == 0) { sH = 0; sM = 0; }
        __syncthreads();
        const int q = blockIdx.x - 192;
        const int QW = (BB * LL / 4) / 4;   // 4352 words per quarter
        const unsigned int* p = maskw + q * QW;
        int lh = 0, lm = 0;
        #pragma unroll 4
        for (int i = tid; i < QW; i += 128) {
            unsigned int w = p[i];
            unsigned int b0 = w & 0xFFu, b1 = (w >> 8) & 0xFFu,
                         b2 = (w >> 16) & 0xFFu, b3 = (w >> 24) & 0xFFu;
            if (b0 > 1u || b1 > 1u || b2 > 1u || b3 > 1u) lh = 1;
            if ((w & 0xFFFFFF00u) != 0u) lm = 1;
        }
        if (lh) atomicOr(&sH, 1);
        if (lm) atomicOr(&sM, 1);
        __syncthreads();
        if (tid == 0) { g_fHigh[q] = sH; g_fMulti[q] = sM; }
    }
}

// ---------------------------------------------------------------------------
// Kernel 2: mega. grid (128 b, 4 c) x 256 threads, >=4 blocks/SM guaranteed
// (all 512 blocks co-resident -> spin barriers cannot deadlock).
//   Phase A: score chunk -> g_S
//   barrier 1 (per b, all 4 chunks)
//   Phase B: softmax (redundant per block) + slf_attn chunk + weighted sum
//            -> g_upart
//   barrier 2 (per b): last arriving block finalizes: u sum, proj = u@W2,
//            residual + LayerNorm; resets counters for next graph replay.
// ---------------------------------------------------------------------------
__global__ __launch_bounds__(256, 4) void mega_kernel(
    const float* __restrict__ node,    // [B,T,H]
    const float* __restrict__ neigh,   // [B,N*T,H]
    const void*  __restrict__ maskraw, // [B,L]
    const float* __restrict__ prjb,
    const float* __restrict__ gamma,
    const float* __restrict__ beta,
    const int*   __restrict__ stepp,
    float* __restrict__ outp)
{
    __shared__ float m_sm[NHEAD * HH];       // 2 KB (reused as u_sm in finalize)
    __shared__ float SA[NHEAD * LL];         // 8.5 KB
    __shared__ float part[8 * NHEAD * HH];   // 16 KB
    __shared__ float red[8];
    __shared__ float red2[8];
    __shared__ int   isLast;

    const int tid = threadIdx.x;
    const int b = blockIdx.x;
    const int c = blockIdx.y;
    const int lane = tid & 31;
    const int wid = tid >> 5;
    const float NEG_INF = __int_as_float(0xff800000u);

    const float4* nodeB  = reinterpret_cast<const float4*>(node  + (size_t)b * TT * HH);
    const float4* neighB = reinterpret_cast<const float4*>(neigh + (size_t)b * NNEI * TT * HH);

    // ======== Phase A: scores for l in [c*CL, (c+1)*CL) ========
    {
        const int mode = mask_mode();
        m_sm[tid]       = g_m[((size_t)(tid >> 7) * 128 + b) * 128 + (tid & 127)];
        m_sm[tid + 256] = g_m[((size_t)((tid + 256) >> 7) * 128 + b) * 128 + ((tid + 256) & 127)];
        __syncthreads();

        float4 mr0 = reinterpret_cast<const float4*>(m_sm)[0 * 32 + lane];
        float4 mr1 = reinterpret_cast<const float4*>(m_sm)[1 * 32 + lane];
        float4 mr2 = reinterpret_cast<const float4*>(m_sm)[2 * 32 + lane];
        float4 mr3 = reinterpret_cast<const float4*>(m_sm)[3 * 32 + lane];

        const int lbase = c * CL + wid * 17;
        const float4* r0 = (lbase < TT) ? (nodeB + (size_t)lbase * 32)
                                        : (neighB + (size_t)(lbase - TT) * 32);
        float4 v = r0[lane];
        #pragma unroll 1
        for (int j = 0; j < 17; j++) {
            float4 vn = make_float4(0, 0, 0, 0);
            if (j < 16) {
                int ln = lbase + j + 1;
                const float4* rn = (ln < TT) ? (nodeB + (size_t)ln * 32)
                                             : (neighB + (size_t)(ln - TT) * 32);
                vn = rn[lane];
            }
            int l = lbase + j;
            float s0 = v.x * mr0.x + v.y * mr0.y + v.z * mr0.z + v.w * mr0.w;
            float s1 = v.x * mr1.x + v.y * mr1.y + v.z * mr1.z + v.w * mr1.w;
            float s2 = v.x * mr2.x + v.y * mr2.y + v.z * mr2.z + v.w * mr2.w;
            float s3 = v.x * mr3.x + v.y * mr3.y + v.z * mr3.z + v.w * mr3.w;
            s0 += __shfl_xor_sync(0xffffffffu, s0, 1);  s0 += __shfl_xor_sync(0xffffffffu, s0, 2);
            s1 += __shfl_xor_sync(0xffffffffu, s1, 1);  s1 += __shfl_xor_sync(0xffffffffu, s1, 2);
            s2 += __shfl_xor_sync(0xffffffffu, s2, 1);  s2 += __shfl_xor_sync(0xffffffffu, s2, 2);
            s3 += __shfl_xor_sync(0xffffffffu, s3, 1);  s3 += __shfl_xor_sync(0xffffffffu, s3, 2);
            int q = lane & 3;
            float w = (q == 0) ? s0 : (q == 1) ? s1 : (q == 2) ? s2 : s3;
            w += __shfl_xor_sync(0xffffffffu, w, 4);
            w += __shfl_xor_sync(0xffffffffu, w, 8);
            w += __shfl_xor_sync(0xffffffffu, w, 16);
            if (lane < 4) {
                size_t mi = (size_t)b * LL + l;
                bool mk;
                if (mode == 0)      mk = (reinterpret_cast<const int*>(maskraw)[mi] != 0);
                else if (mode == 1) mk = (reinterpret_cast<const unsigned char*>(maskraw)[mi] != 0);
                else                mk = (reinterpret_cast<const float*>(maskraw)[mi] != 0.f);
                g_S[((size_t)b * NHEAD + lane) * LL + l] = mk ? NEG_INF : w * SCALE;
            }
            v = vn;
        }
    }

    // ======== barrier 1: all chunks of b have written S ========
    __threadfence();
    __syncthreads();
    if (tid == 0) {
        atomicAdd(&g_cnt1[b], 1);
        while (atomicAdd(&g_cnt1[b], 0) < CH) __nanosleep(32);
    }
    __syncthreads();
    __threadfence();

    // ======== Phase B: softmax + slf_attn chunk + weighted sum ========
    {
        const float4* Sg = reinterpret_cast<const float4*>(g_S + (size_t)b * NHEAD * LL);
        float4* SA4 = reinterpret_cast<float4*>(SA);
        for (int i = tid; i < NHEAD * LL / 4; i += 256) SA4[i] = Sg[i];
    }
    __syncthreads();

    {
        const int n = wid >> 1;
        const int half = wid & 1;
        float mx = NEG_INF;
        for (int l = half * 32 + lane; l < LL; l += 64) mx = fmaxf(mx, SA[n * LL + l]);
        mx = warpRedMax(mx);
        if (lane == 0) red[wid] = mx;
        __syncthreads();
        mx = fmaxf(red[n * 2], red[n * 2 + 1]);

        float sm = 0.f;
        for (int l = half * 32 + lane; l < LL; l += 64) {
            float e = __expf(SA[n * LL + l] - mx);
            SA[n * LL + l] = e;
            sm += e;
        }
        sm = warpRedSum(sm);
        if (lane == 0) red2[wid] = sm;
        __syncthreads();
        float inv = 1.f / (red2[n * 2] + red2[n * 2 + 1]);
        for (int l = half * 32 + lane; l < LL; l += 64) SA[n * LL + l] *= inv;
    }
    __syncthreads();

    if (tid < CL) {
        int l = c * CL + tid;
        outp[BB * HH + (size_t)b * LL + l] = SA[l] + SA[LL + l] + SA[2 * LL + l] + SA[3 * LL + l];
    }

    {
        const int l0 = c * CL + wid * 17;
        float4 a0 = make_float4(0, 0, 0, 0), a1 = a0, a2 = a0, a3 = a0;
        const float4* rr = (l0 < TT) ? (nodeB + (size_t)l0 * 32)
                                     : (neighB + (size_t)(l0 - TT) * 32);
        float4 v = rr[lane];
        #pragma unroll 1
        for (int j = 0; j < 17; j++) {
            float4 vn = make_float4(0, 0, 0, 0);
            if (j < 16) {
                int ln = l0 + j + 1;
                const float4* rn = (ln < TT) ? (nodeB + (size_t)ln * 32)
                                             : (neighB + (size_t)(ln - TT) * 32);
                vn = rn[lane];
            }
            int l = l0 + j;
            float c0 = SA[l], c1 = SA[LL + l], c2 = SA[2 * LL + l], c3 = SA[3 * LL + l];
            a0.x += c0 * v.x; a0.y += c0 * v.y; a0.z += c0 * v.z; a0.w += c0 * v.w;
            a1.x += c1 * v.x; a1.y += c1 * v.y; a1.z += c1 * v.z; a1.w += c1 * v.w;
            a2.x += c2 * v.x; a2.y += c2 * v.y; a2.z += c2 * v.z; a2.w += c2 * v.w;
            a3.x += c3 * v.x; a3.y += c3 * v.y; a3.z += c3 * v.z; a3.w += c3 * v.w;
            v = vn;
        }
        float4* P = reinterpret_cast<float4*>(part);
        P[(wid * 4 + 0) * 32 + lane] = a0;
        P[(wid * 4 + 1) * 32 + lane] = a1;
        P[(wid * 4 + 2) * 32 + lane] = a2;
        P[(wid * 4 + 3) * 32 + lane] = a3;
    }
    __syncthreads();
    {
        #pragma unroll
        for (int r = 0; r < 2; r++) {
            int idx = tid + r * 256;
            int n = idx >> 7, h = idx & 127;
            float u = 0.f;
            #pragma unroll
            for (int g = 0; g < 8; g++) u += part[(g * 4 + n) * 128 + h];
            g_upart[((size_t)c * BB + b) * 512 + idx] = u;
        }
    }

    // ======== barrier 2: last chunk of b finalizes ========
    __threadfence();
    __syncthreads();
    if (tid == 0) isLast = (atomicAdd(&g_cnt2[b], 1) == CH - 1);
    __syncthreads();
    if (!isLast) return;
    __threadfence();

    // ======== finalize: u sum -> proj = u@W2 -> residual + LayerNorm ========
    float* u_sm = m_sm;  // reuse
    #pragma unroll
    for (int r = 0; r < 2; r++) {
        int idx = tid + r * 256;
        u_sm[idx] = g_upart[((size_t)0 * BB + b) * 512 + idx]
                  + g_upart[((size_t)1 * BB + b) * 512 + idx]
                  + g_upart[((size_t)2 * BB + b) * 512 + idx]
                  + g_upart[((size_t)3 * BB + b) * 512 + idx];
    }
    __syncthreads();

    // projection: warp wid handles i in [wid*64, wid*64+64); lane owns float4 of e
    {
        const float4* W24 = reinterpret_cast<const float4*>(g_W2);
        float4 acc = make_float4(0, 0, 0, 0);
        const int i0 = wid * 64;
        #pragma unroll 8
        for (int k = 0; k < 64; k++) {
            int i = i0 + k;
            float uv = u_sm[i];
            float4 wv = W24[(size_t)i * 32 + lane];
            acc.x += uv * wv.x; acc.y += uv * wv.y; acc.z += uv * wv.z; acc.w += uv * wv.w;
        }
        reinterpret_cast<float4*>(part)[wid * 32 + lane] = acc;  // part[wid*128+e]
    }
    __syncthreads();

    {
        const int ts = stepp[0];
        float x = 0.f;
        if (tid < 128) {
            float p = 0.f;
            #pragma unroll
            for (int w = 0; w < 8; w++) p += part[w * 128 + tid];
            x = p + prjb[tid] + node[(size_t)b * (TT * HH) + (size_t)ts * HH + tid];
        }
        float ws = warpRedSum(x);
        if (tid < 128 && lane == 0) red[wid] = ws;
        __syncthreads();
        float mean = (red[0] + red[1] + red[2] + red[3]) * (1.f / 128.f);
        float d = x - mean;
        float wq = warpRedSum(d * d);
        if (tid < 128 && lane == 0) red2[wid] = wq;
        __syncthreads();
        if (tid < 128) {
            float var = (red2[0] + red2[1] + red2[2] + red2[3]) * (1.f / 128.f);
            outp[(size_t)b * 128 + tid] = d * rsqrtf(var + 1e-6f) * gamma[tid] + beta[tid];
        }
    }

    // reset barriers for next graph replay (all peers have passed both stages)
    if (tid == 0) { g_cnt1[b] = 0; g_cnt2[b] = 0; }
}

extern "C" void kernel_launch(void* const* d_in, const int* in_sizes, int n_in,
                              void* d_out, int out_size)
{
    const float* node  = (const float*)d_in[0];
    const float* neigh = (const float*)d_in[1];
    const void*  mask  = d_in[2];
    const int*   step  = (const int*)d_in[3];
    const float* wqs   = (const float*)d_in[4];
    const float* wks   = (const float*)d_in[5];
    const float* wvs   = (const float*)d_in[6];
    const float* prjw  = (const float*)d_in[7];
    const float* prjb  = (const float*)d_in[8];
    const float* gamma = (const float*)d_in[9];
    const float* beta  = (const float*)d_in[10];
    float* outp = (float*)d_out;

    prep_kernel<<<196, 128>>>(node, wqs, wks, wvs, prjw,
                              (const unsigned int*)mask, step);
    mega_kernel<<<dim3(128, CH), 256>>>(node, neigh, mask, prjb, gamma, beta,
                                        step, outp);
}